// round 5
// baseline (speedup 1.0000x reference)
#include <cuda_runtime.h>
#include <cuda_bf16.h>
#include <cstdint>

#define KEPS   0.001f
#define BH     64
#define SLEN   4096
#define DDIM   64
#define SPLITS 16
#define SCHUNK (SLEN / SPLITS)     // 256
#define NROWS  72                  // partial/B rows: 64 kv + ksum + 7 pad

// ---------------- scratch (__device__ globals; allocation-free rule) -------
__device__ float         g_pkv[SPLITS * BH * NROWS * DDIM];
__device__ __nv_bfloat16 g_bhi[BH * NROWS * DDIM];
__device__ __nv_bfloat16 g_blo[BH * NROWS * DDIM];

// ---------------- helpers ---------------------------------------------------
__device__ __forceinline__ uint32_t s2u(const void* p) {
    uint32_t a;
    asm("{ .reg .u64 t; cvta.to.shared.u64 t, %1; cvt.u32.u64 %0, t; }"
        : "=r"(a) : "l"(p));
    return a;
}
__device__ __forceinline__ void mma16816(float* c, const uint32_t* a, const uint32_t* b) {
    asm volatile(
        "mma.sync.aligned.m16n8k16.row.col.f32.bf16.bf16.f32 "
        "{%0,%1,%2,%3}, {%4,%5,%6,%7}, {%8,%9}, {%0,%1,%2,%3};"
        : "+f"(c[0]), "+f"(c[1]), "+f"(c[2]), "+f"(c[3])
        : "r"(a[0]), "r"(a[1]), "r"(a[2]), "r"(a[3]), "r"(b[0]), "r"(b[1]));
}
__device__ __forceinline__ void ldsm_x4_t(uint32_t* r, uint32_t addr) {
    asm volatile("ldmatrix.sync.aligned.m8n8.x4.trans.shared.b16 {%0,%1,%2,%3}, [%4];"
        : "=r"(r[0]), "=r"(r[1]), "=r"(r[2]), "=r"(r[3]) : "r"(addr));
}
__device__ __forceinline__ void ldsm_x2(uint32_t* r, uint32_t addr) {
    asm volatile("ldmatrix.sync.aligned.m8n8.x2.shared.b16 {%0,%1}, [%2];"
        : "=r"(r[0]), "=r"(r[1]) : "r"(addr));
}
__device__ __forceinline__ void ldsm_x2_t(uint32_t* r, uint32_t addr) {
    asm volatile("ldmatrix.sync.aligned.m8n8.x2.trans.shared.b16 {%0,%1}, [%2];"
        : "=r"(r[0]), "=r"(r[1]) : "r"(addr));
}
__device__ __forceinline__ void bfsplit(float x, __nv_bfloat16& h, __nv_bfloat16& l) {
    h = __float2bfloat16(x);
    l = __float2bfloat16(x - __bfloat162float(h));
}
__device__ __forceinline__ uint32_t packhi(float a, float b) {
    __nv_bfloat162 p; p.x = __float2bfloat16(a); p.y = __float2bfloat16(b);
    return *(uint32_t*)&p;
}

// ---------------------------------------------------------------------------
// Phase 1 (HMMA): partial M[e,d] = sum_s v_ext[s,e] * k_eff[s,d] over S-chunk.
//   v_ext: cols 0-63 = v, col 64 = 1 (-> ksum), 65-95 = 0.
// grid = (BH, SPLITS), block = 256 (8 warps = 4 d-groups x 2 e-groups).
// Register-staged double buffering of the 64-row window.
// ---------------------------------------------------------------------------
__global__ __launch_bounds__(256, 2) void k_phase1(
    const float* __restrict__ key,
    const float* __restrict__ value,
    const float* __restrict__ mask)
{
    __shared__ __nv_bfloat16 skh[64][72], skl[64][72];   // k_eff hi/lo
    __shared__ __nv_bfloat16 svh[64][96], svl[64][96];   // v_ext hi/lo

    const int bh    = blockIdx.x;
    const int split = blockIdx.y;
    const int b     = bh >> 4;
    const int t     = threadIdx.x;
    const int warp  = t >> 5;
    const int lane  = t & 31;
    const int dg    = warp & 3;          // d-group: 16 cols
    const int eg    = warp >> 2;         // e-group: 48 rows

    // init v pad cols 64..95 (constant across buffers)
    for (int i = t; i < 64 * 32; i += 256) {
        int row = i >> 5, col = 64 + (i & 31);
        svh[row][col] = __float2bfloat16(col == 64 ? 1.0f : 0.0f);
        svl[row][col] = __float2bfloat16(0.0f);
    }

    float acc[3][2][4];
#pragma unroll
    for (int i = 0; i < 3; i++)
#pragma unroll
        for (int j = 0; j < 2; j++)
#pragma unroll
            for (int q = 0; q < 4; q++) acc[i][j][q] = 0.0f;

    const float* kp = key   + (size_t)bh * SLEN * DDIM;
    const float* vp = value + (size_t)bh * SLEN * DDIM;
    const float* mp = mask  + (size_t)b * SLEN;
    const int s0 = split * SCHUNK;

    const uint32_t a_kh = s2u(&skh[0][0]), a_kl = s2u(&skl[0][0]);
    const uint32_t a_vh = s2u(&svh[0][0]), a_vl = s2u(&svl[0][0]);

    const int grp = lane >> 3, jj = lane & 7, l15 = lane & 15;
    const int myrow = t >> 4;            // staging row base (0..15), +16 per i
    const int myc4  = (t & 15) * 4;

    float4 kst[4], vst[4];
    float  mst[4];

    // stage buffer 0
#pragma unroll
    for (int i = 0; i < 4; i++) {
        int row = myrow + i * 16;
        kst[i] = *(const float4*)(kp + (size_t)(s0 + row) * DDIM + myc4);
        vst[i] = *(const float4*)(vp + (size_t)(s0 + row) * DDIM + myc4);
        mst[i] = mp[s0 + row];
    }

    for (int buf = 0; buf < SCHUNK / 64; buf++) {
        __syncthreads();                  // smem free (prev MMA reads done)
#pragma unroll
        for (int i = 0; i < 4; i++) {
            int row = myrow + i * 16;
            float m = mst[i];
            float x0 = (fmaxf(kst[i].x, 0.0f) + KEPS) * m;
            float x1 = (fmaxf(kst[i].y, 0.0f) + KEPS) * m;
            float x2 = (fmaxf(kst[i].z, 0.0f) + KEPS) * m;
            float x3 = (fmaxf(kst[i].w, 0.0f) + KEPS) * m;
            __nv_bfloat16 h0,h1,h2,h3,l0,l1,l2,l3;
            bfsplit(x0,h0,l0); bfsplit(x1,h1,l1); bfsplit(x2,h2,l2); bfsplit(x3,h3,l3);
            __nv_bfloat162 p;
            p.x=h0; p.y=h1; *(__nv_bfloat162*)&skh[row][myc4]   = p;
            p.x=h2; p.y=h3; *(__nv_bfloat162*)&skh[row][myc4+2] = p;
            p.x=l0; p.y=l1; *(__nv_bfloat162*)&skl[row][myc4]   = p;
            p.x=l2; p.y=l3; *(__nv_bfloat162*)&skl[row][myc4+2] = p;

            bfsplit(vst[i].x,h0,l0); bfsplit(vst[i].y,h1,l1);
            bfsplit(vst[i].z,h2,l2); bfsplit(vst[i].w,h3,l3);
            p.x=h0; p.y=h1; *(__nv_bfloat162*)&svh[row][myc4]   = p;
            p.x=h2; p.y=h3; *(__nv_bfloat162*)&svh[row][myc4+2] = p;
            p.x=l0; p.y=l1; *(__nv_bfloat162*)&svl[row][myc4]   = p;
            p.x=l2; p.y=l3; *(__nv_bfloat162*)&svl[row][myc4+2] = p;
        }
        __syncthreads();

        // prefetch next buffer while MMAs run
        if (buf + 1 < SCHUNK / 64) {
            const int sg = s0 + (buf + 1) * 64;
#pragma unroll
            for (int i = 0; i < 4; i++) {
                int row = myrow + i * 16;
                kst[i] = *(const float4*)(kp + (size_t)(sg + row) * DDIM + myc4);
                vst[i] = *(const float4*)(vp + (size_t)(sg + row) * DDIM + myc4);
                mst[i] = mp[sg + row];
            }
        }

#pragma unroll
        for (int ks = 0; ks < 64; ks += 16) {
            uint32_t Bh[2][2], Bl[2][2];
#pragma unroll
            for (int nt = 0; nt < 2; nt++) {
                int d0 = dg * 16 + nt * 8;
                ldsm_x2_t(Bh[nt], a_kh + (uint32_t)(((ks + l15) * 72 + d0) * 2));
                ldsm_x2_t(Bl[nt], a_kl + (uint32_t)(((ks + l15) * 72 + d0) * 2));
            }
            const int vrow = ks + jj + ((grp >> 1) << 3);
#pragma unroll
            for (int mt = 0; mt < 3; mt++) {
                int e0 = eg * 48 + mt * 16 + ((grp & 1) << 3);
                uint32_t Ah[4], Al[4];
                ldsm_x4_t(Ah, a_vh + (uint32_t)((vrow * 96 + e0) * 2));
                ldsm_x4_t(Al, a_vl + (uint32_t)((vrow * 96 + e0) * 2));
#pragma unroll
                for (int nt = 0; nt < 2; nt++) {
                    mma16816(acc[mt][nt], Ah, Bh[nt]);
                    mma16816(acc[mt][nt], Ah, Bl[nt]);
                    mma16816(acc[mt][nt], Al, Bh[nt]);
                }
            }
        }
    }

    // store fp32 partials [e<72][d 64]
    float* pkv = g_pkv + ((size_t)(split * BH + bh)) * NROWS * DDIM;
    const int r = lane >> 2, c2 = (lane & 3) * 2;
#pragma unroll
    for (int mt = 0; mt < 3; mt++)
#pragma unroll
        for (int nt = 0; nt < 2; nt++) {
            int e0 = eg * 48 + mt * 16 + r;
            int d  = dg * 16 + nt * 8 + c2;
            if (e0 < NROWS)
                *(float2*)(pkv + e0 * DDIM + d) = make_float2(acc[mt][nt][0], acc[mt][nt][1]);
            if (e0 + 8 < NROWS)
                *(float2*)(pkv + (e0 + 8) * DDIM + d) = make_float2(acc[mt][nt][2], acc[mt][nt][3]);
        }
}

// ---------------------------------------------------------------------------
// Reduce over splits -> bf16 hi/lo B tiles [72][64]. grid = (BH, 2), block 256.
// ---------------------------------------------------------------------------
__global__ __launch_bounds__(256) void k_reduce()
{
    const int bh   = blockIdx.x;
    const int half = blockIdx.y;
    const int t    = threadIdx.x;
#pragma unroll
    for (int j = 0; j < 9; j++) {
        int idx = half * 2304 + t + j * 256;      // 0..4607
        float s = 0.0f;
#pragma unroll
        for (int sp = 0; sp < SPLITS; sp++)
            s += g_pkv[((size_t)(sp * BH + bh)) * NROWS * DDIM + idx];
        __nv_bfloat16 h, l;
        bfsplit(s, h, l);
        g_bhi[(size_t)bh * NROWS * DDIM + idx] = h;
        g_blo[(size_t)bh * NROWS * DDIM + idx] = l;
    }
}

// ---------------------------------------------------------------------------
// Phase 2 (HMMA): D[128s x 72n] = Q_eff[128x64] . B[72x64]^T ; col 64 = denom.
// Q loaded DIRECTLY into A-fragment layout via LDG.64 (no smem round-trip).
// grid = (SLEN/128, BH), block = 128.
// ---------------------------------------------------------------------------
__global__ __launch_bounds__(128, 3) void k_phase2(
    const float* __restrict__ query,
    float* __restrict__ out)
{
    __shared__ __nv_bfloat16 sbh[NROWS * NROWS];   // B hi, stride 72
    __shared__ __nv_bfloat16 sbl[NROWS * NROWS];   // B lo

    const uint32_t a_bh = s2u(sbh), a_bl = s2u(sbl);
    const int t    = threadIdx.x;
    const int warp = t >> 5;
    const int lane = t & 31;
    const int s0   = blockIdx.x * 128;
    const int bh   = blockIdx.y;

    // ---- B tiles ----
    {
        const uint4* gh = (const uint4*)(g_bhi + (size_t)bh * NROWS * DDIM);
        const uint4* gl = (const uint4*)(g_blo + (size_t)bh * NROWS * DDIM);
#pragma unroll
        for (int i = 0; i < 5; i++) {
            int lin = t + i * 128;
            if (lin < 576) {
                int row = lin >> 3, col = (lin & 7) * 8;
                *(uint4*)((char*)sbh + (row * 72 + col) * 2) = gh[lin];
                *(uint4*)((char*)sbl + (row * 72 + col) * 2) = gl[lin];
            }
        }
    }
    __syncthreads();

    float acc[2][9][4];
#pragma unroll
    for (int i = 0; i < 2; i++)
#pragma unroll
        for (int j = 0; j < 9; j++)
#pragma unroll
            for (int q = 0; q < 4; q++) acc[i][j][q] = 0.0f;

    const int l15 = lane & 15;
    const int fr  = lane >> 2;           // frag row 0..7
    const int fc  = (lane & 3) * 2;      // frag col pair

    const float* qp = query + (size_t)bh * SLEN * DDIM;

    // software pipeline over it = ks*2 + mt
    float2 st0, st1, st2, st3;
    {
        int r0 = s0 + warp * 32 + fr;    // it=0: ks=0, mt=0
        st0 = *(const float2*)(qp + (size_t)r0 * DDIM + fc);
        st1 = *(const float2*)(qp + (size_t)(r0 + 8) * DDIM + fc);
        st2 = *(const float2*)(qp + (size_t)r0 * DDIM + fc + 8);
        st3 = *(const float2*)(qp + (size_t)(r0 + 8) * DDIM + fc + 8);
    }

    uint32_t Bh[9][2], Bl[9][2];
    int cur_ks = -1;

#pragma unroll
    for (int it = 0; it < 8; it++) {
        const int ks = it >> 1;
        const int k0 = ks * 16;
        if (ks != cur_ks) {
            cur_ks = ks;
#pragma unroll
            for (int nt = 0; nt < 9; nt++) {
                uint32_t off = (uint32_t)(((nt * 8 + (l15 & 7)) * 72 + k0 + ((l15 >> 3) << 3)) * 2);
                ldsm_x2(Bh[nt], a_bh + off);
                ldsm_x2(Bl[nt], a_bl + off);
            }
        }

        float2 c0 = st0, c1 = st1, c2 = st2, c3 = st3;
        if (it < 7) {
            int nit = it + 1;
            int nks = nit >> 1, nmt = nit & 1;
            int r0 = s0 + warp * 32 + nmt * 16 + fr;
            int cc = nks * 16 + fc;
            st0 = *(const float2*)(qp + (size_t)r0 * DDIM + cc);
            st1 = *(const float2*)(qp + (size_t)(r0 + 8) * DDIM + cc);
            st2 = *(const float2*)(qp + (size_t)r0 * DDIM + cc + 8);
            st3 = *(const float2*)(qp + (size_t)(r0 + 8) * DDIM + cc + 8);
        }

        // convert: relu+eps, bf16 hi/lo, pack to A frags
        uint32_t Ah[4], Al[4];
        {
            float x0 = fmaxf(c0.x, 0.0f) + KEPS, x1 = fmaxf(c0.y, 0.0f) + KEPS;
            float y0 = fmaxf(c1.x, 0.0f) + KEPS, y1 = fmaxf(c1.y, 0.0f) + KEPS;
            float z0 = fmaxf(c2.x, 0.0f) + KEPS, z1 = fmaxf(c2.y, 0.0f) + KEPS;
            float w0 = fmaxf(c3.x, 0.0f) + KEPS, w1 = fmaxf(c3.y, 0.0f) + KEPS;
            Ah[0] = packhi(x0, x1);
            Ah[1] = packhi(y0, y1);
            Ah[2] = packhi(z0, z1);
            Ah[3] = packhi(w0, w1);
            Al[0] = packhi(x0 - __bfloat162float(__float2bfloat16(x0)),
                           x1 - __bfloat162float(__float2bfloat16(x1)));
            Al[1] = packhi(y0 - __bfloat162float(__float2bfloat16(y0)),
                           y1 - __bfloat162float(__float2bfloat16(y1)));
            Al[2] = packhi(z0 - __bfloat162float(__float2bfloat16(z0)),
                           z1 - __bfloat162float(__float2bfloat16(z1)));
            Al[3] = packhi(w0 - __bfloat162float(__float2bfloat16(w0)),
                           w1 - __bfloat162float(__float2bfloat16(w1)));
        }

        const int mt = it & 1;
#pragma unroll
        for (int nt = 0; nt < 9; nt++) {
            mma16816(acc[mt][nt], Ah, Bh[nt]);
            mma16816(acc[mt][nt], Ah, Bl[nt]);
            mma16816(acc[mt][nt], Al, Bh[nt]);
        }
    }

    // ---- epilogue: divide by denom (col 64 = acc[mt][8][0]/[2]) + direct STG
#pragma unroll
    for (int mt = 0; mt < 2; mt++) {
        float dlo = __shfl_sync(0xffffffffu, acc[mt][8][0], lane & 28);
        float dhi = __shfl_sync(0xffffffffu, acc[mt][8][2], lane & 28);
        float ilo = 1.0f / dlo;
        float ihi = 1.0f / dhi;
        int r0 = s0 + warp * 32 + mt * 16 + fr;
        float* ob0 = out + ((size_t)bh * SLEN + r0) * DDIM;
        float* ob1 = out + ((size_t)bh * SLEN + r0 + 8) * DDIM;
#pragma unroll
        for (int nt = 0; nt < 8; nt++) {
            int c = nt * 8 + fc;
            *(float2*)(ob0 + c) = make_float2(acc[mt][nt][0] * ilo, acc[mt][nt][1] * ilo);
            *(float2*)(ob1 + c) = make_float2(acc[mt][nt][2] * ihi, acc[mt][nt][3] * ihi);
        }
    }
}

// ---------------------------------------------------------------------------
extern "C" void kernel_launch(void* const* d_in, const int* in_sizes, int n_in,
                              void* d_out, int out_size)
{
    const float* query = (const float*)d_in[0];
    const float* key   = (const float*)d_in[1];
    const float* value = (const float*)d_in[2];
    const float* mask  = (const float*)d_in[3];
    float* out = (float*)d_out;

    k_phase1<<<dim3(BH, SPLITS), 256>>>(key, value, mask);
    k_reduce<<<dim3(BH, 2), 256>>>();
    k_phase2<<<dim3(SLEN / 128, BH), 128>>>(query, out);
}

// round 6
// speedup vs baseline: 1.3399x; 1.3399x over previous
#include <cuda_runtime.h>
#include <cuda_bf16.h>
#include <cstdint>

#define KEPS   0.001f
#define BH     64
#define SLEN   4096
#define DDIM   64
#define SPLITS 16
#define SCHUNK (SLEN / SPLITS)     // 256
#define NROWS  72                  // partial/B rows: 64 kv + ksum + 7 pad

// ---------------- scratch (__device__ globals; allocation-free rule) -------
__device__ float         g_pkv[SPLITS * BH * NROWS * DDIM];
__device__ __nv_bfloat16 g_bhi[BH * NROWS * DDIM];
__device__ __nv_bfloat16 g_blo[BH * NROWS * DDIM];

// ---------------- helpers ---------------------------------------------------
__device__ __forceinline__ uint32_t s2u(const void* p) {
    uint32_t a;
    asm("{ .reg .u64 t; cvta.to.shared.u64 t, %1; cvt.u32.u64 %0, t; }"
        : "=r"(a) : "l"(p));
    return a;
}
__device__ __forceinline__ void mma16816(float* c, const uint32_t* a, const uint32_t* b) {
    asm volatile(
        "mma.sync.aligned.m16n8k16.row.col.f32.bf16.bf16.f32 "
        "{%0,%1,%2,%3}, {%4,%5,%6,%7}, {%8,%9}, {%0,%1,%2,%3};"
        : "+f"(c[0]), "+f"(c[1]), "+f"(c[2]), "+f"(c[3])
        : "r"(a[0]), "r"(a[1]), "r"(a[2]), "r"(a[3]), "r"(b[0]), "r"(b[1]));
}
__device__ __forceinline__ void ldsm_x4_t(uint32_t* r, uint32_t addr) {
    asm volatile("ldmatrix.sync.aligned.m8n8.x4.trans.shared.b16 {%0,%1,%2,%3}, [%4];"
        : "=r"(r[0]), "=r"(r[1]), "=r"(r[2]), "=r"(r[3]) : "r"(addr));
}
__device__ __forceinline__ void ldsm_x2(uint32_t* r, uint32_t addr) {
    asm volatile("ldmatrix.sync.aligned.m8n8.x2.shared.b16 {%0,%1}, [%2];"
        : "=r"(r[0]), "=r"(r[1]) : "r"(addr));
}
__device__ __forceinline__ void ldsm_x2_t(uint32_t* r, uint32_t addr) {
    asm volatile("ldmatrix.sync.aligned.m8n8.x2.trans.shared.b16 {%0,%1}, [%2];"
        : "=r"(r[0]), "=r"(r[1]) : "r"(addr));
}
__device__ __forceinline__ void bfsplit(float x, __nv_bfloat16& h, __nv_bfloat16& l) {
    h = __float2bfloat16(x);
    l = __float2bfloat16(x - __bfloat162float(h));
}
__device__ __forceinline__ uint32_t packhi(float a, float b) {
    __nv_bfloat162 p; p.x = __float2bfloat16(a); p.y = __float2bfloat16(b);
    return *(uint32_t*)&p;
}

// ---------------------------------------------------------------------------
// Phase 1 (HMMA): partial M[e,d] = sum_s v_ext[s,e] * k_eff[s,d] over S-chunk.
//   v_ext: cols 0-63 = v, col 64 = 1 (-> ksum), 65-79 = 0.
// grid = (BH, SPLITS), block = 128 (4 warps; warp = 16-wide d-group).
// 32-row window; next window LDGs issued before the MMA block (latency hide).
// ---------------------------------------------------------------------------
__global__ __launch_bounds__(128, 3) void k_phase1(
    const float* __restrict__ key,
    const float* __restrict__ value,
    const float* __restrict__ mask)
{
    __shared__ __nv_bfloat16 skh[32][72], skl[32][72];   // k_eff hi/lo
    __shared__ __nv_bfloat16 svh[32][88], svl[32][88];   // v_ext hi/lo

    const int bh    = blockIdx.x;
    const int split = blockIdx.y;
    const int b     = bh >> 4;
    const int t     = threadIdx.x;
    const int warp  = t >> 5;            // d-group
    const int lane  = t & 31;

    // init v pad cols 64..87 (constant across windows)
    for (int i = t; i < 32 * 24; i += 128) {
        int row = i / 24, col = 64 + (i % 24);
        svh[row][col] = __float2bfloat16(col == 64 ? 1.0f : 0.0f);
        svl[row][col] = __float2bfloat16(0.0f);
    }

    float acc[5][2][4];
#pragma unroll
    for (int i = 0; i < 5; i++)
#pragma unroll
        for (int j = 0; j < 2; j++)
#pragma unroll
            for (int q = 0; q < 4; q++) acc[i][j][q] = 0.0f;

    const float* kp = key   + (size_t)bh * SLEN * DDIM;
    const float* vp = value + (size_t)bh * SLEN * DDIM;
    const float* mp = mask  + (size_t)b * SLEN;
    const int s0 = split * SCHUNK;

    const uint32_t a_kh = s2u(&skh[0][0]), a_kl = s2u(&skl[0][0]);
    const uint32_t a_vh = s2u(&svh[0][0]), a_vl = s2u(&svl[0][0]);

    const int grp = lane >> 3, jj = lane & 7, l15 = lane & 15;
    const int myrow = t >> 4;            // 0..7 (+8i for i<4 -> 32 rows)
    const int myc4  = (t & 15) * 4;

    float4 kst[4], vst[4];
    float  mst[4];

    // stage window 0
#pragma unroll
    for (int i = 0; i < 4; i++) {
        int row = myrow + i * 8;
        kst[i] = *(const float4*)(kp + (size_t)(s0 + row) * DDIM + myc4);
        vst[i] = *(const float4*)(vp + (size_t)(s0 + row) * DDIM + myc4);
        mst[i] = mp[s0 + row];
    }

    const int nsteps = SCHUNK / 32;      // 8
    for (int step = 0; step < nsteps; step++) {
        __syncthreads();                 // previous MMA reads done
#pragma unroll
        for (int i = 0; i < 4; i++) {
            int row = myrow + i * 8;
            float m = mst[i];
            float x0 = (fmaxf(kst[i].x, 0.0f) + KEPS) * m;
            float x1 = (fmaxf(kst[i].y, 0.0f) + KEPS) * m;
            float x2 = (fmaxf(kst[i].z, 0.0f) + KEPS) * m;
            float x3 = (fmaxf(kst[i].w, 0.0f) + KEPS) * m;
            __nv_bfloat16 h0,h1,h2,h3,l0,l1,l2,l3;
            bfsplit(x0,h0,l0); bfsplit(x1,h1,l1); bfsplit(x2,h2,l2); bfsplit(x3,h3,l3);
            __nv_bfloat162 p;
            p.x=h0; p.y=h1; *(__nv_bfloat162*)&skh[row][myc4]   = p;
            p.x=h2; p.y=h3; *(__nv_bfloat162*)&skh[row][myc4+2] = p;
            p.x=l0; p.y=l1; *(__nv_bfloat162*)&skl[row][myc4]   = p;
            p.x=l2; p.y=l3; *(__nv_bfloat162*)&skl[row][myc4+2] = p;

            bfsplit(vst[i].x,h0,l0); bfsplit(vst[i].y,h1,l1);
            bfsplit(vst[i].z,h2,l2); bfsplit(vst[i].w,h3,l3);
            p.x=h0; p.y=h1; *(__nv_bfloat162*)&svh[row][myc4]   = p;
            p.x=h2; p.y=h3; *(__nv_bfloat162*)&svh[row][myc4+2] = p;
            p.x=l0; p.y=l1; *(__nv_bfloat162*)&svl[row][myc4]   = p;
            p.x=l2; p.y=l3; *(__nv_bfloat162*)&svl[row][myc4+2] = p;
        }
        __syncthreads();

        // prefetch next window while MMAs run below
        if (step + 1 < nsteps) {
            const int sg = s0 + (step + 1) * 32;
#pragma unroll
            for (int i = 0; i < 4; i++) {
                int row = myrow + i * 8;
                kst[i] = *(const float4*)(kp + (size_t)(sg + row) * DDIM + myc4);
                vst[i] = *(const float4*)(vp + (size_t)(sg + row) * DDIM + myc4);
                mst[i] = mp[sg + row];
            }
        }

#pragma unroll
        for (int ks = 0; ks < 32; ks += 16) {
            uint32_t Bh[2][2], Bl[2][2];
#pragma unroll
            for (int nt = 0; nt < 2; nt++) {
                int d0 = warp * 16 + nt * 8;
                ldsm_x2_t(Bh[nt], a_kh + (uint32_t)(((ks + l15) * 72 + d0) * 2));
                ldsm_x2_t(Bl[nt], a_kl + (uint32_t)(((ks + l15) * 72 + d0) * 2));
            }
            const int vrow = ks + jj + ((grp >> 1) << 3);
#pragma unroll
            for (int mt = 0; mt < 5; mt++) {
                int e0 = mt * 16 + ((grp & 1) << 3);
                uint32_t Ah[4], Al[4];
                ldsm_x4_t(Ah, a_vh + (uint32_t)((vrow * 88 + e0) * 2));
                if (mt < 4)
                    ldsm_x4_t(Al, a_vl + (uint32_t)((vrow * 88 + e0) * 2));
#pragma unroll
                for (int nt = 0; nt < 2; nt++) {
                    mma16816(acc[mt][nt], Ah, Bh[nt]);
                    mma16816(acc[mt][nt], Ah, Bl[nt]);
                    if (mt < 4) mma16816(acc[mt][nt], Al, Bh[nt]);
                }
            }
        }
    }

    // store fp32 partials [e<72][d 64]
    float* pkv = g_pkv + ((size_t)(split * BH + bh)) * NROWS * DDIM;
    const int r = lane >> 2, c2 = (lane & 3) * 2;
#pragma unroll
    for (int mt = 0; mt < 5; mt++)
#pragma unroll
        for (int nt = 0; nt < 2; nt++) {
            int e = mt * 16 + r;
            int d = warp * 16 + nt * 8 + c2;
            *(float2*)(pkv + e * DDIM + d) = make_float2(acc[mt][nt][0], acc[mt][nt][1]);
            if (mt < 4)
                *(float2*)(pkv + (e + 8) * DDIM + d) = make_float2(acc[mt][nt][2], acc[mt][nt][3]);
        }
}

// ---------------------------------------------------------------------------
// Reduce over splits -> bf16 hi/lo B tiles [72][64]. grid = BH, block = 288.
// float4 loads: 1152 float4 per bh.
// ---------------------------------------------------------------------------
__global__ __launch_bounds__(288) void k_reduce()
{
    const int bh = blockIdx.x;
    const int t  = threadIdx.x;
#pragma unroll
    for (int j = 0; j < 4; j++) {
        int lin = t + j * 288;               // 0..1151 (float4 idx)
        float4 s = make_float4(0.f, 0.f, 0.f, 0.f);
#pragma unroll
        for (int sp = 0; sp < SPLITS; sp++) {
            float4 v = *(const float4*)(g_pkv + ((size_t)(sp * BH + bh)) * NROWS * DDIM + lin * 4);
            s.x += v.x; s.y += v.y; s.z += v.z; s.w += v.w;
        }
        __nv_bfloat16 h0,h1,h2,h3,l0,l1,l2,l3;
        bfsplit(s.x,h0,l0); bfsplit(s.y,h1,l1); bfsplit(s.z,h2,l2); bfsplit(s.w,h3,l3);
        __nv_bfloat162 ph0; ph0.x=h0; ph0.y=h1;
        __nv_bfloat162 ph1; ph1.x=h2; ph1.y=h3;
        __nv_bfloat162 pl0; pl0.x=l0; pl0.y=l1;
        __nv_bfloat162 pl1; pl1.x=l2; pl1.y=l3;
        uint2 uh = make_uint2(*(uint32_t*)&ph0, *(uint32_t*)&ph1);
        uint2 ul = make_uint2(*(uint32_t*)&pl0, *(uint32_t*)&pl1);
        *(uint2*)(g_bhi + (size_t)bh * NROWS * DDIM + lin * 4) = uh;
        *(uint2*)(g_blo + (size_t)bh * NROWS * DDIM + lin * 4) = ul;
    }
}

// ---------------------------------------------------------------------------
// Phase 2 (HMMA): D[128s x 72n] = Q_eff[128x64] . B[72x64]^T ; col 64 = denom.
// Q loaded DIRECTLY into A-fragment layout via LDG.64, 2-deep pipeline.
// grid = (SLEN/128, BH), block = 128.
// ---------------------------------------------------------------------------
__global__ __launch_bounds__(128, 3) void k_phase2(
    const float* __restrict__ query,
    float* __restrict__ out)
{
    __shared__ __nv_bfloat16 sbh[NROWS * NROWS];   // B hi, stride 72
    __shared__ __nv_bfloat16 sbl[NROWS * NROWS];   // B lo

    const uint32_t a_bh = s2u(sbh), a_bl = s2u(sbl);
    const int t    = threadIdx.x;
    const int warp = t >> 5;
    const int lane = t & 31;
    const int s0   = blockIdx.x * 128;
    const int bh   = blockIdx.y;

    // ---- B tiles ----
    {
        const uint4* gh = (const uint4*)(g_bhi + (size_t)bh * NROWS * DDIM);
        const uint4* gl = (const uint4*)(g_blo + (size_t)bh * NROWS * DDIM);
#pragma unroll
        for (int i = 0; i < 5; i++) {
            int lin = t + i * 128;
            if (lin < 576) {
                int row = lin >> 3, col = (lin & 7) * 8;
                *(uint4*)((char*)sbh + (row * 72 + col) * 2) = gh[lin];
                *(uint4*)((char*)sbl + (row * 72 + col) * 2) = gl[lin];
            }
        }
    }
    __syncthreads();

    float acc[2][9][4];
#pragma unroll
    for (int i = 0; i < 2; i++)
#pragma unroll
        for (int j = 0; j < 9; j++)
#pragma unroll
            for (int q = 0; q < 4; q++) acc[i][j][q] = 0.0f;

    const int l15 = lane & 15;
    const int fr  = lane >> 2;           // frag row 0..7
    const int fc  = (lane & 3) * 2;      // frag col pair

    const float* qp = query + (size_t)bh * SLEN * DDIM;

    // 2-deep software pipeline over it = ks*2 + mt  (mt = it&1, ks = it>>1)
    float2 st[2][4];
#pragma unroll
    for (int pre = 0; pre < 2; pre++) {
        int r0 = s0 + warp * 32 + (pre & 1) * 16 + fr;
        int cc = (pre >> 1) * 16 + fc;
        st[pre][0] = *(const float2*)(qp + (size_t)r0 * DDIM + cc);
        st[pre][1] = *(const float2*)(qp + (size_t)(r0 + 8) * DDIM + cc);
        st[pre][2] = *(const float2*)(qp + (size_t)r0 * DDIM + cc + 8);
        st[pre][3] = *(const float2*)(qp + (size_t)(r0 + 8) * DDIM + cc + 8);
    }

    uint32_t Bh[9][2], Bl[9][2];
    int cur_ks = -1;

#pragma unroll
    for (int it = 0; it < 8; it++) {
        const int ks = it >> 1;
        const int k0 = ks * 16;
        if (ks != cur_ks) {
            cur_ks = ks;
#pragma unroll
            for (int nt = 0; nt < 9; nt++) {
                uint32_t off = (uint32_t)(((nt * 8 + (l15 & 7)) * 72 + k0 + ((l15 >> 3) << 3)) * 2);
                ldsm_x2(Bh[nt], a_bh + off);
                ldsm_x2(Bl[nt], a_bl + off);
            }
        }

        float2 c0 = st[it & 1][0], c1 = st[it & 1][1];
        float2 c2 = st[it & 1][2], c3 = st[it & 1][3];
        if (it + 2 < 8) {
            int nit = it + 2;
            int r0 = s0 + warp * 32 + (nit & 1) * 16 + fr;
            int cc = (nit >> 1) * 16 + fc;
            st[it & 1][0] = *(const float2*)(qp + (size_t)r0 * DDIM + cc);
            st[it & 1][1] = *(const float2*)(qp + (size_t)(r0 + 8) * DDIM + cc);
            st[it & 1][2] = *(const float2*)(qp + (size_t)r0 * DDIM + cc + 8);
            st[it & 1][3] = *(const float2*)(qp + (size_t)(r0 + 8) * DDIM + cc + 8);
        }

        // convert: relu+eps, bf16 hi/lo, pack to A frags
        uint32_t Ah[4], Al[4];
        {
            float x0 = fmaxf(c0.x, 0.0f) + KEPS, x1 = fmaxf(c0.y, 0.0f) + KEPS;
            float y0 = fmaxf(c1.x, 0.0f) + KEPS, y1 = fmaxf(c1.y, 0.0f) + KEPS;
            float z0 = fmaxf(c2.x, 0.0f) + KEPS, z1 = fmaxf(c2.y, 0.0f) + KEPS;
            float w0 = fmaxf(c3.x, 0.0f) + KEPS, w1 = fmaxf(c3.y, 0.0f) + KEPS;
            Ah[0] = packhi(x0, x1);
            Ah[1] = packhi(y0, y1);
            Ah[2] = packhi(z0, z1);
            Ah[3] = packhi(w0, w1);
            Al[0] = packhi(x0 - __bfloat162float(__float2bfloat16(x0)),
                           x1 - __bfloat162float(__float2bfloat16(x1)));
            Al[1] = packhi(y0 - __bfloat162float(__float2bfloat16(y0)),
                           y1 - __bfloat162float(__float2bfloat16(y1)));
            Al[2] = packhi(z0 - __bfloat162float(__float2bfloat16(z0)),
                           z1 - __bfloat162float(__float2bfloat16(z1)));
            Al[3] = packhi(w0 - __bfloat162float(__float2bfloat16(w0)),
                           w1 - __bfloat162float(__float2bfloat16(w1)));
        }

        const int mt = it & 1;
#pragma unroll
        for (int nt = 0; nt < 9; nt++) {
            mma16816(acc[mt][nt], Ah, Bh[nt]);
            mma16816(acc[mt][nt], Ah, Bl[nt]);
            mma16816(acc[mt][nt], Al, Bh[nt]);
        }
    }

    // ---- epilogue: divide by denom (col 64 = acc[mt][8][0]/[2]) + direct STG
#pragma unroll
    for (int mt = 0; mt < 2; mt++) {
        float dlo = __shfl_sync(0xffffffffu, acc[mt][8][0], lane & 28);
        float dhi = __shfl_sync(0xffffffffu, acc[mt][8][2], lane & 28);
        float ilo = 1.0f / dlo;
        float ihi = 1.0f / dhi;
        int r0 = s0 + warp * 32 + mt * 16 + fr;
        float* ob0 = out + ((size_t)bh * SLEN + r0) * DDIM;
        float* ob1 = out + ((size_t)bh * SLEN + r0 + 8) * DDIM;
#pragma unroll
        for (int nt = 0; nt < 8; nt++) {
            int c = nt * 8 + fc;
            *(float2*)(ob0 + c) = make_float2(acc[mt][nt][0] * ilo, acc[mt][nt][1] * ilo);
            *(float2*)(ob1 + c) = make_float2(acc[mt][nt][2] * ihi, acc[mt][nt][3] * ihi);
        }
    }
}

// ---------------------------------------------------------------------------
extern "C" void kernel_launch(void* const* d_in, const int* in_sizes, int n_in,
                              void* d_out, int out_size)
{
    const float* query = (const float*)d_in[0];
    const float* key   = (const float*)d_in[1];
    const float* value = (const float*)d_in[2];
    const float* mask  = (const float*)d_in[3];
    float* out = (float*)d_out;

    k_phase1<<<dim3(BH, SPLITS), 128>>>(key, value, mask);
    k_reduce<<<BH, 288>>>();
    k_phase2<<<dim3(SLEN / 128, BH), 128>>>(query, out);
}